// round 15
// baseline (speedup 1.0000x reference)
#include <cuda_runtime.h>
#include <cuda_fp16.h>
#include <cstdint>

#define B_TOT   4096
#define N_IN    512
#define N_TOT   2048
#define N_EVAL  1536
#define N_OUTC  256
#define NPH     24
#define MROWS   32
#define NCTA    128
#define NTHREADS 160      // warps 0-3 compute, warp 4 serial
#define DENSE_T 128

// Pre-baked fp16 tiles, stride-72 rows (144 B): conflict-free scalar LDS.
// A tile: 32 x 144 = 4608 B ; B tile (single fp16): 64 x 144 = 9216 B
__device__ __align__(256) char g_AT[128u * 32u * 4608u];    // ~18.9 MB
__device__ __align__(256) char g_BT[24u * 32u * 9216u];     // ~7 MB

#define AT_TILE(rb, c) (g_AT + (size_t)((rb) * 32 + (c)) * 4608u)
#define BT_TILE(q, c)  (g_BT + (size_t)((q) * 32 + (c)) * 9216u)

// ---- shared memory layout (bytes) ----
// Pair-ring: 3 slots, each slot = 2 chunks.
#define SM_A    0                 // 3 x 9216  (2 x 4608 per slot)
#define SM_B    27648             // 3 x 18432 (2 x 9216 per slot)
#define SM_DEPA 82944             // 4608   dep A (serial warp writes ONLY)
#define SM_DEPB 87552             // 9216   dep B
#define SM_SWB  96768             // 16384  in-block weights f32 [64][64]
#define SM_SB   113152            // 256    biases
#define SM_SZ   113408            // 32*65*4 Z tile
#define SMEM_BYTES 121728

#define BAR_ALL()   asm volatile("bar.sync 1, 160;" ::: "memory")
#define BAR_DENSE() asm volatile("bar.sync 2, 128;" ::: "memory")
#define CP_COMMIT() asm volatile("cp.async.commit_group;" ::: "memory")
#define CP_WAIT0()  asm volatile("cp.async.wait_group 0;" ::: "memory")
#define CP_WAIT1()  asm volatile("cp.async.wait_group 1;" ::: "memory")

__device__ __forceinline__ uint32_t smem_u32(const void* p) {
    uint32_t a;
    asm("{ .reg .u64 t; cvta.to.shared.u64 t, %1; cvt.u32.u64 %0, t; }"
        : "=r"(a) : "l"(p));
    return a;
}
__device__ __forceinline__ void cp16(uint32_t d, const void* s) {
    asm volatile("cp.async.cg.shared.global [%0], [%1], 16;"
                 :: "r"(d), "l"(s) : "memory");
}
__device__ __forceinline__ void hmma(float* d, const uint32_t* a, const uint32_t* b) {
    asm volatile("mma.sync.aligned.m16n8k16.row.col.f32.f16.f16.f32 "
                 "{%0,%1,%2,%3}, {%4,%5,%6,%7}, {%8,%9}, {%0,%1,%2,%3};"
                 : "+f"(d[0]), "+f"(d[1]), "+f"(d[2]), "+f"(d[3])
                 : "r"(a[0]), "r"(a[1]), "r"(a[2]), "r"(a[3]),
                   "r"(b[0]), "r"(b[1]));
}
__device__ __forceinline__ uint32_t packh2(float v0, float v1) {
    __half h0 = __float2half(v0), h1 = __float2half(v1);
    return (uint32_t)__half_as_ushort(h0) | ((uint32_t)__half_as_ushort(h1) << 16);
}
__device__ __forceinline__ float sigmoid5(float z) {
    float t5 = fminf(fmaxf(5.0f * z, -60.0f), 60.0f);
    float e;
    asm("ex2.approx.f32 %0, %1;" : "=f"(e) : "f"(t5 * (-1.4426950408889634f)));
    float sig;
    asm("rcp.approx.f32 %0, %1;" : "=f"(sig) : "f"(1.0f + e));
    return sig;
}

// ---- prep: bake fp16 tiles ----
__global__ void __launch_bounds__(256) prep_X(const float* __restrict__ x) {
    const int rb = blockIdx.x, c = blockIdx.y;   // 128 x 8
    char* base = AT_TILE(rb, c);
    for (int i = threadIdx.x; i < 32 * 32; i += 256) {
        int r = i >> 5, kp = i & 31;
        const float* src = x + (size_t)(rb * 32 + r) * N_IN + c * 64 + kp * 2;
        *(uint32_t*)(base + (uint32_t)(r * 144 + kp * 4)) = packh2(src[0], src[1]);
    }
}
__global__ void __launch_bounds__(256) prep_W(const float* __restrict__ W) {
    const int q = blockIdx.x, c = blockIdx.y;    // 24 x 32
    if (c > 7 + q) return;
    char* base = BT_TILE(q, c);
    for (int i = threadIdx.x; i < 64 * 32; i += 256) {
        int n = i >> 5, kp = i & 31;
        const float* src = W + (size_t)(q * 64 + n) * N_TOT + c * 64 + kp * 2;
        *(uint32_t*)(base + (uint32_t)(n * 144 + kp * 4)) = packh2(src[0], src[1]);
    }
}

extern __shared__ __align__(16) char smem[];

__global__ void __launch_bounds__(NTHREADS, 1)
ff_kernel(const float* __restrict__ W, const float* __restrict__ bias,
          float* __restrict__ out) {
    const int t = threadIdx.x;
    const int wid = t >> 5, lane = t & 31;
    const int rb = blockIdx.x;
    const uint32_t sb32 = smem_u32(smem);
    float* sZ  = (float*)(smem + SM_SZ);
    float* sWb = (float*)(smem + SM_SWB);
    float* sB  = (float*)(smem + SM_SB);

    if (wid < 4) {
        // ============ COMPUTE WARPS: 16x32 tile each (2x2 layout) ============
        const int row0 = (wid & 1) * 16;
        const int col0 = (wid >> 1) * 32;
        float acc[4][4] = {};

        auto pf_A = [&](uint32_t doff, const char* src) {
            for (int i = t; i < 288; i += DENSE_T) cp16(sb32 + doff + i * 16, src + i * 16);
        };
        auto pf_B = [&](uint32_t doff, const char* src) {
            for (int i = t; i < 576; i += DENSE_T) cp16(sb32 + doff + i * 16, src + i * 16);
        };
        auto mac_chunk = [&](const char* A, const char* Bt) {
            #pragma unroll
            for (int kk = 0; kk < 4; ++kk) {
                const char* pa = A + (row0 + (lane >> 2)) * 144 + (lane & 3) * 4 + kk * 32;
                uint32_t ah[4] = { *(const uint32_t*)(pa),
                                   *(const uint32_t*)(pa + 1152),
                                   *(const uint32_t*)(pa + 16),
                                   *(const uint32_t*)(pa + 1168) };
                #pragma unroll
                for (int nt = 0; nt < 4; ++nt) {
                    const char* pb = Bt + (col0 + nt * 8 + (lane >> 2)) * 144
                                     + (lane & 3) * 4 + kk * 32;
                    uint32_t bh[2] = { *(const uint32_t*)(pb),
                                       *(const uint32_t*)(pb + 16) };
                    hmma(acc[nt], ah, bh);
                }
            }
        };
        // stage pair jp (chunks 2jp, 2jp+1) into slot s
        auto stage_pair = [&](int q, int jp, int nch, uint32_t s) {
            int c0 = 2 * jp;
            pf_A(SM_A + s * 9216u, AT_TILE(rb, c0));
            pf_B(SM_B + s * 18432u, BT_TILE(q, c0));
            if (c0 + 1 < nch) {
                pf_A(SM_A + s * 9216u + 4608u, AT_TILE(rb, c0 + 1));
                pf_B(SM_B + s * 18432u + 9216u, BT_TILE(q, c0 + 1));
            }
        };
        auto chunk_loop = [&](int q, int nch, bool doDep) {
            const int np = (nch + 1) / 2;
            stage_pair(q, 0, nch, 0); CP_COMMIT();
            stage_pair(q, 1, nch, 1); CP_COMMIT();
            for (int jp = 0; jp < np; ++jp) {
                CP_WAIT1();             // pair jp's group drained
                BAR_DENSE();            // publish pair jp; slot (jp+2)%3 free
                if (jp + 2 < np) {
                    stage_pair(q, jp + 2, nch, (uint32_t)((jp + 2) % 3));
                } else if (doDep && jp + 2 == np) {
                    pf_B(SM_DEPB, BT_TILE(q, 7 + q));   // dep WEIGHTS only
                }
                CP_COMMIT();            // exactly one group per iter (may be empty)
                uint32_t s = (uint32_t)(jp % 3);
                mac_chunk(smem + SM_A + s * 9216u, smem + SM_B + s * 18432u);
                if (2 * jp + 1 < nch)
                    mac_chunk(smem + SM_A + s * 9216u + 4608u,
                              smem + SM_B + s * 18432u + 9216u);
            }
        };

        // ---- prologue: phase 0 (8 chunks, all from x) ----
        chunk_loop(0, 8, false);

        for (int p = 0; p < NPH; ++p) {
            const int e0 = p * 64, S = N_IN + e0;

            // segment A: stage sWb/sB, dep mma, Z write
            for (int i = t; i < 1024; i += DENSE_T) {
                int n = i >> 4, j = i & 15;
                cp16(sb32 + SM_SWB + (uint32_t)i * 16,
                     W + (size_t)(e0 + n) * N_TOT + S + j * 4);
            }
            if (t < 16) cp16(sb32 + SM_SB + (uint32_t)t * 16, bias + e0 + t * 4);
            CP_COMMIT();
            CP_WAIT0();                 // sWb + sB + dep-B drained
            BAR_DENSE();                // + all warps done with ring macs
            if (p > 0) mac_chunk(smem + SM_DEPA, smem + SM_DEPB);
            {
                int m = row0 + (lane >> 2), cb = (lane & 3) * 2;
                #pragma unroll
                for (int nt = 0; nt < 4; ++nt) {
                    float* z = sZ + m * 65 + col0 + nt * 8 + cb;
                    z[0]          = acc[nt][0];
                    z[1]          = acc[nt][1];
                    z[8 * 65]     = acc[nt][2];
                    z[8 * 65 + 1] = acc[nt][3];
                    acc[nt][0] = acc[nt][1] = acc[nt][2] = acc[nt][3] = 0.f;
                }
            }
            BAR_ALL();     // serial warp may start (Z, sWb, sB ready)

            if (p < NPH - 1)
                chunk_loop(p + 1, 8 + p, true);
            BAR_ALL();     // phase end (serial done; SM_DEPA ready)
        }
    } else {
        // =================== SERIAL WARP (lane = row) ===================
        const int r = lane;
        for (int p = 0; p < NPH; ++p) {
            const int e0 = p * 64;
            BAR_ALL();     // Z + sWb + sB ready

            float o[64];
            const float* zrow = sZ + r * 65;
            #pragma unroll
            for (int k = 0; k < 64; ++k) {
                float z  = zrow[k] + sB[k];
                float z1 = 0.0f;
                const float* wk = sWb + k * 64;
                #pragma unroll
                for (int j = 0; j + 1 < k; j += 2) {
                    z  = fmaf(o[j],     wk[j],     z);
                    z1 = fmaf(o[j + 1], wk[j + 1], z1);
                }
                if (k & 1) z = fmaf(o[k - 1], wk[k - 1], z);
                o[k] = sigmoid5(z + z1);
            }

            if (p < NPH - 1) {
                // dep A (smem, sole source next phase) + global tile (phases >= p+2)
                char* sH = smem + SM_DEPA;
                char* gH = AT_TILE(rb, 8 + p);
                #pragma unroll
                for (int kp = 0; kp < 32; ++kp) {
                    uint32_t hp = packh2(o[2 * kp], o[2 * kp + 1]);
                    uint32_t off = (uint32_t)(r * 144 + kp * 4);
                    *(uint32_t*)(sH + off) = hp;
                    *(uint32_t*)(gH + off) = hp;
                }
            }
            if (p >= 20) {
                float* orow = out + (size_t)(rb * 32 + r) * N_OUTC + (e0 - 1280);
                #pragma unroll
                for (int k = 0; k < 64; ++k) orow[k] = o[k];
            }
            __threadfence();   // g_AT writes visible to later cp.async (L2 path)
            BAR_ALL();         // phase end
        }
    }
}

extern "C" void kernel_launch(void* const* d_in, const int* in_sizes, int n_in,
                              void* d_out, int out_size) {
    const float* x = (const float*)d_in[0];   // [4096, 512]
    const float* W = (const float*)d_in[1];   // [1536, 2048]
    const float* b = (const float*)d_in[2];   // [1536]
    float* out = (float*)d_out;               // [4096, 256]
    (void)in_sizes; (void)n_in; (void)out_size;

    prep_X<<<dim3(128, 8), 256>>>(x);
    prep_W<<<dim3(24, 32), 256>>>(W);

    cudaFuncSetAttribute(ff_kernel, cudaFuncAttributeMaxDynamicSharedMemorySize,
                         SMEM_BYTES);
    ff_kernel<<<NCTA, NTHREADS, SMEM_BYTES>>>(W, b, out);
}

// round 16
// speedup vs baseline: 1.5128x; 1.5128x over previous
#include <cuda_runtime.h>
#include <cuda_fp16.h>
#include <cstdint>

#define B_TOT   4096
#define N_IN    512
#define N_TOT   2048
#define N_EVAL  1536
#define N_OUTC  256
#define NPH     24
#define MROWS   32
#define NCTA    128
#define NTHREADS 160      // warps 0-3 compute, warp 4 serial
#define DENSE_T 128

// Pre-baked fp16 tiles, stride-72 rows (144 B): conflict-free scalar LDS.
// A tile: 32 x 144 = 4608 B ; B tile: 64 x 144 = 9216 B
__device__ __align__(256) char g_AT[128u * 32u * 4608u];    // ~18.9 MB
__device__ __align__(256) char g_BT[24u * 32u * 9216u];     // ~7 MB

#define AT_TILE(rb, c) (g_AT + (size_t)((rb) * 32 + (c)) * 4608u)
#define BT_TILE(q, c)  (g_BT + (size_t)((q) * 32 + (c)) * 9216u)

// ---- shared memory layout (bytes) ----
#define SM_A    0                 // 4 x 4608   A ring
#define SM_B    18432             // 4 x 9216   B ring
#define SM_DEPA 55296             // 4608   dep A (serial warp writes ONLY)
#define SM_DEPB 59904             // 9216   dep B
#define SM_SWB  69120             // 16384  in-block weights f32 [64][64]
#define SM_SB   85504             // 256    biases
#define SM_SZ   85760             // 32*65*4 Z tile
#define SMEM_BYTES 94080

#define BAR_ALL()   asm volatile("bar.sync 1, 160;" ::: "memory")
#define BAR_DENSE() asm volatile("bar.sync 2, 128;" ::: "memory")
#define CP_COMMIT() asm volatile("cp.async.commit_group;" ::: "memory")
#define CP_WAIT0()  asm volatile("cp.async.wait_group 0;" ::: "memory")
#define CP_WAIT2()  asm volatile("cp.async.wait_group 2;" ::: "memory")

__device__ __forceinline__ uint32_t smem_u32(const void* p) {
    uint32_t a;
    asm("{ .reg .u64 t; cvta.to.shared.u64 t, %1; cvt.u32.u64 %0, t; }"
        : "=r"(a) : "l"(p));
    return a;
}
__device__ __forceinline__ void cp16(uint32_t d, const void* s) {
    asm volatile("cp.async.cg.shared.global [%0], [%1], 16;"
                 :: "r"(d), "l"(s) : "memory");
}
__device__ __forceinline__ void hmma(float* d, const uint32_t* a, const uint32_t* b) {
    asm volatile("mma.sync.aligned.m16n8k16.row.col.f32.f16.f16.f32 "
                 "{%0,%1,%2,%3}, {%4,%5,%6,%7}, {%8,%9}, {%0,%1,%2,%3};"
                 : "+f"(d[0]), "+f"(d[1]), "+f"(d[2]), "+f"(d[3])
                 : "r"(a[0]), "r"(a[1]), "r"(a[2]), "r"(a[3]),
                   "r"(b[0]), "r"(b[1]));
}
__device__ __forceinline__ uint32_t packh2(float v0, float v1) {
    __half h0 = __float2half(v0), h1 = __float2half(v1);
    return (uint32_t)__half_as_ushort(h0) | ((uint32_t)__half_as_ushort(h1) << 16);
}
__device__ __forceinline__ float sigmoid5(float z) {
    float t5 = fminf(fmaxf(5.0f * z, -60.0f), 60.0f);
    float e;
    asm("ex2.approx.f32 %0, %1;" : "=f"(e) : "f"(t5 * (-1.4426950408889634f)));
    float sig;
    asm("rcp.approx.f32 %0, %1;" : "=f"(sig) : "f"(1.0f + e));
    return sig;
}

// ---- prep: bake fp16 tiles ----
__global__ void __launch_bounds__(256) prep_X(const float* __restrict__ x) {
    const int rb = blockIdx.x, c = blockIdx.y;   // 128 x 8
    char* base = AT_TILE(rb, c);
    for (int i = threadIdx.x; i < 32 * 32; i += 256) {
        int r = i >> 5, kp = i & 31;
        const float* src = x + (size_t)(rb * 32 + r) * N_IN + c * 64 + kp * 2;
        *(uint32_t*)(base + (uint32_t)(r * 144 + kp * 4)) = packh2(src[0], src[1]);
    }
}
__global__ void __launch_bounds__(256) prep_W(const float* __restrict__ W) {
    const int q = blockIdx.x, c = blockIdx.y;    // 24 x 32
    if (c > 7 + q) return;
    char* base = BT_TILE(q, c);
    for (int i = threadIdx.x; i < 64 * 32; i += 256) {
        int n = i >> 5, kp = i & 31;
        const float* src = W + (size_t)(q * 64 + n) * N_TOT + c * 64 + kp * 2;
        *(uint32_t*)(base + (uint32_t)(n * 144 + kp * 4)) = packh2(src[0], src[1]);
    }
}

extern __shared__ __align__(16) char smem[];

__global__ void __launch_bounds__(NTHREADS, 1)
ff_kernel(const float* __restrict__ W, const float* __restrict__ bias,
          float* __restrict__ out) {
    const int t = threadIdx.x;
    const int wid = t >> 5, lane = t & 31;
    const int rb = blockIdx.x;
    const uint32_t sb32 = smem_u32(smem);
    float* sZ  = (float*)(smem + SM_SZ);
    float* sWb = (float*)(smem + SM_SWB);
    float* sB  = (float*)(smem + SM_SB);

    if (wid < 4) {
        // ============ COMPUTE WARPS: 16x32 tile each (2x2 layout) ============
        const int row0 = (wid & 1) * 16;
        const int col0 = (wid >> 1) * 32;
        // 8 independent HMMA chains: even-kk / odd-kk partials per nt.
        float accE[4][4] = {}, accO[4][4] = {};

        auto pf_A = [&](uint32_t doff, const char* src) {
            for (int i = t; i < 288; i += DENSE_T) cp16(sb32 + doff + i * 16, src + i * 16);
        };
        auto pf_B = [&](uint32_t doff, const char* src) {
            for (int i = t; i < 576; i += DENSE_T) cp16(sb32 + doff + i * 16, src + i * 16);
        };
        auto mac_chunk = [&](const char* A, const char* Bt) {
            #pragma unroll
            for (int kk = 0; kk < 4; ++kk) {
                const char* pa = A + (row0 + (lane >> 2)) * 144 + (lane & 3) * 4 + kk * 32;
                uint32_t ah[4] = { *(const uint32_t*)(pa),
                                   *(const uint32_t*)(pa + 1152),
                                   *(const uint32_t*)(pa + 16),
                                   *(const uint32_t*)(pa + 1168) };
                float (*acc)[4] = (kk & 1) ? accO : accE;
                #pragma unroll
                for (int nt = 0; nt < 4; ++nt) {
                    const char* pb = Bt + (col0 + nt * 8 + (lane >> 2)) * 144
                                     + (lane & 3) * 4 + kk * 32;
                    uint32_t bh[2] = { *(const uint32_t*)(pb),
                                       *(const uint32_t*)(pb + 16) };
                    hmma(acc[nt], ah, bh);
                }
            }
        };
        auto chunk_loop = [&](int q, int nch, bool doDep) {
            pf_A(SM_A, AT_TILE(rb, 0));             pf_B(SM_B, BT_TILE(q, 0));
            CP_COMMIT();
            pf_A(SM_A + 4608u, AT_TILE(rb, 1));     pf_B(SM_B + 9216u, BT_TILE(q, 1));
            CP_COMMIT();
            for (int c = 0; c < nch; ++c) {
                if (c + 2 < nch) {
                    uint32_t s = (uint32_t)((c + 2) & 3);
                    pf_A(SM_A + s * 4608u, AT_TILE(rb, c + 2));
                    pf_B(SM_B + s * 9216u, BT_TILE(q, c + 2));
                } else if (doDep && c + 2 == nch) {
                    pf_B(SM_DEPB, BT_TILE(q, 7 + q));   // dep WEIGHTS only
                }
                CP_COMMIT();            // exactly one group per iter (may be empty)
                CP_WAIT2();             // group for chunk c complete
                BAR_DENSE();            // publish cp data + protect ring reuse
                mac_chunk(smem + SM_A + (size_t)(c & 3) * 4608u,
                          smem + SM_B + (size_t)(c & 3) * 9216u);
            }
        };

        // ---- prologue: phase 0 (8 chunks, all from x) ----
        chunk_loop(0, 8, false);

        for (int p = 0; p < NPH; ++p) {
            const int e0 = p * 64, S = N_IN + e0;

            // segment A: stage sWb/sB, dep mma, Z write
            for (int i = t; i < 1024; i += DENSE_T) {
                int n = i >> 4, j = i & 15;
                cp16(sb32 + SM_SWB + (uint32_t)i * 16,
                     W + (size_t)(e0 + n) * N_TOT + S + j * 4);
            }
            if (t < 16) cp16(sb32 + SM_SB + (uint32_t)t * 16, bias + e0 + t * 4);
            CP_COMMIT();
            CP_WAIT0();                 // sWb + sB + dep-B drained
            BAR_DENSE();                // + all warps done reading A/B ring
            if (p > 0) mac_chunk(smem + SM_DEPA, smem + SM_DEPB);
            {
                int m = row0 + (lane >> 2), cb = (lane & 3) * 2;
                #pragma unroll
                for (int nt = 0; nt < 4; ++nt) {
                    float* z = sZ + m * 65 + col0 + nt * 8 + cb;
                    z[0]          = accE[nt][0] + accO[nt][0];
                    z[1]          = accE[nt][1] + accO[nt][1];
                    z[8 * 65]     = accE[nt][2] + accO[nt][2];
                    z[8 * 65 + 1] = accE[nt][3] + accO[nt][3];
                    accE[nt][0] = accE[nt][1] = accE[nt][2] = accE[nt][3] = 0.f;
                    accO[nt][0] = accO[nt][1] = accO[nt][2] = accO[nt][3] = 0.f;
                }
            }
            BAR_ALL();     // serial warp may start (Z, sWb, sB ready)

            if (p < NPH - 1)
                chunk_loop(p + 1, 8 + p, true);
            BAR_ALL();     // phase end (serial done; SM_DEPA ready)
        }
    } else {
        // =================== SERIAL WARP (lane = row) ===================
        const int r = lane;
        for (int p = 0; p < NPH; ++p) {
            const int e0 = p * 64;
            BAR_ALL();     // Z + sWb + sB ready

            float o[64];
            const float* zrow = sZ + r * 65;
            #pragma unroll
            for (int k = 0; k < 64; ++k) {
                float z  = zrow[k] + sB[k];
                float z1 = 0.0f;
                const float* wk = sWb + k * 64;
                #pragma unroll
                for (int j = 0; j + 1 < k; j += 2) {
                    z  = fmaf(o[j],     wk[j],     z);
                    z1 = fmaf(o[j + 1], wk[j + 1], z1);
                }
                if (k & 1) z = fmaf(o[k - 1], wk[k - 1], z);
                o[k] = sigmoid5(z + z1);
            }

            if (p < NPH - 1) {
                // dep A (smem, sole source next phase) + global tile (phases >= p+2)
                char* sH = smem + SM_DEPA;
                char* gH = AT_TILE(rb, 8 + p);
                #pragma unroll
                for (int kp = 0; kp < 32; ++kp) {
                    uint32_t hp = packh2(o[2 * kp], o[2 * kp + 1]);
                    uint32_t off = (uint32_t)(r * 144 + kp * 4);
                    *(uint32_t*)(sH + off) = hp;
                    *(uint32_t*)(gH + off) = hp;
                }
            }
            if (p >= 20) {
                float* orow = out + (size_t)(rb * 32 + r) * N_OUTC + (e0 - 1280);
                #pragma unroll
                for (int k = 0; k < 64; ++k) orow[k] = o[k];
            }
            __threadfence();   // g_AT writes visible to later cp.async (L2 path)
            BAR_ALL();         // phase end
        }
    }
}

extern "C" void kernel_launch(void* const* d_in, const int* in_sizes, int n_in,
                              void* d_out, int out_size) {
    const float* x = (const float*)d_in[0];   // [4096, 512]
    const float* W = (const float*)d_in[1];   // [1536, 2048]
    const float* b = (const float*)d_in[2];   // [1536]
    float* out = (float*)d_out;               // [4096, 256]
    (void)in_sizes; (void)n_in; (void)out_size;

    prep_X<<<dim3(128, 8), 256>>>(x);
    prep_W<<<dim3(24, 32), 256>>>(W);

    cudaFuncSetAttribute(ff_kernel, cudaFuncAttributeMaxDynamicSharedMemorySize,
                         SMEM_BYTES);
    ff_kernel<<<NCTA, NTHREADS, SMEM_BYTES>>>(W, b, out);
}